// round 7
// baseline (speedup 1.0000x reference)
#include <cuda_runtime.h>
#include <cstdint>

#define DDIM 256
#define KC   512
#define BM   128
#define KN   128
#define NMAX 131072
#define SLOTS 16
#define RSTRIDE 528            // smem row stride in bytes (264 bf16) — 33×16B,
                               // (r+u) mod 8 distinct => conflict-free ldmatrix
#define DYN_SMEM (2 * BM * RSTRIDE)   // A tile + B tile = 135168 B

__device__ float g_esq[KC];
__device__ float g_zsq[NMAX];
__device__ int   g_emax_bits;  // max_k sqrt(esq_k) as float bits (monotone >=0)

__device__ __forceinline__ uint32_t sm_u32(const void* p) {
    uint32_t a;
    asm("{ .reg .u64 t; cvta.to.shared.u64 t, %1; cvt.u32.u64 %0, t; }"
        : "=r"(a) : "l"(p));
    return a;
}
#define STS128(a, r0, r1, r2, r3) \
    asm volatile("st.shared.v4.b32 [%0], {%1, %2, %3, %4};" \
                 :: "r"(a), "r"(r0), "r"(r1), "r"(r2), "r"(r3) : "memory")
#define LDMX4(r0, r1, r2, r3, addr) \
    asm volatile("ldmatrix.sync.aligned.m8n8.x4.shared.b16 {%0,%1,%2,%3}, [%4];" \
                 : "=r"(r0), "=r"(r1), "=r"(r2), "=r"(r3) : "r"(addr))
#define MMA16816(c, a0, a1, a2, a3, b0, b1) \
    asm volatile("mma.sync.aligned.m16n8k16.row.col.f32.bf16.bf16.f32 " \
                 "{%0,%1,%2,%3}, {%4,%5,%6,%7}, {%8,%9}, {%0,%1,%2,%3};" \
                 : "+f"((c)[0]), "+f"((c)[1]), "+f"((c)[2]), "+f"((c)[3]) \
                 : "r"(a0), "r"(a1), "r"(a2), "r"(a3), "r"(b0), "r"(b1))

// -------- fused prologue: bitwise-exact sum(x*x) rows (R3-proven order) -----
__global__ __launch_bounds__(128)
void rowsq_all(const float* __restrict__ z, const float* __restrict__ cb,
               int nbz) {
    __shared__ float tile[128][33];
    const int b = blockIdx.x;
    const bool is_cb = (b >= nbz);
    const float* src = is_cb ? cb : z;
    const int r0 = (is_cb ? (b - nbz) : b) * 128;
    const int t = threadIdx.x;
    float acc = 0.f;
    for (int d0 = 0; d0 < DDIM; d0 += 32) {
        __syncthreads();
        for (int e = t; e < 128 * 32; e += 128) {
            int r = e >> 5, c = e & 31;
            tile[r][c] = src[(size_t)(r0 + r) * DDIM + d0 + c];
        }
        __syncthreads();
        #pragma unroll
        for (int c = 0; c < 32; c++) {
            float v = tile[t][c];
            acc = __fadd_rn(acc, __fmul_rn(v, v));
        }
    }
    if (is_cb) {
        g_esq[r0 + t] = acc;
        atomicMax(&g_emax_bits, __float_as_int(sqrtf(acc)));
    } else {
        g_zsq[r0 + t] = acc;
    }
}

// ------------------------------- main kernel -------------------------------
__global__ __launch_bounds__(256)
void vq_main(const float* __restrict__ z, const float* __restrict__ cb,
             float* __restrict__ out, long long qoff4) {
    extern __shared__ __align__(16) char dsm[];
    __shared__ float s_esq[KN];
    __shared__ int   s_cnt[BM];
    __shared__ int   s_candk[BM][SLOTS];
    __shared__ float s_candv[BM][SLOTS];
    __shared__ float s_rowmin[BM];
    __shared__ int   bidx[BM];

    const int tid = threadIdx.x;
    const int w   = tid >> 5;
    const int l   = tid & 31;
    const int m0  = blockIdx.x * BM;
    const uint32_t Ab = sm_u32(dsm);
    const uint32_t Bb = Ab + BM * RSTRIDE;

    if (tid < BM) s_cnt[tid] = 0;

    // ---- load A (z tile): fp32 -> bf16 rn, padded rows ----
    {
        const float* src = z + (size_t)m0 * DDIM;
        #pragma unroll
        for (int it = 0; it < 16; it++) {
            int u = tid + it * 256;               // 0..4095 chunks of 8 elems
            int r = u >> 5, c = u & 31;
            const float* p = src + (size_t)r * DDIM + c * 8;
            float4 f0 = __ldg(reinterpret_cast<const float4*>(p));
            float4 f1 = __ldg(reinterpret_cast<const float4*>(p + 4));
            uint32_t p0, p1, p2, p3;
            asm("cvt.rn.bf16x2.f32 %0, %1, %2;" : "=r"(p0) : "f"(f0.y), "f"(f0.x));
            asm("cvt.rn.bf16x2.f32 %0, %1, %2;" : "=r"(p1) : "f"(f0.w), "f"(f0.z));
            asm("cvt.rn.bf16x2.f32 %0, %1, %2;" : "=r"(p2) : "f"(f1.y), "f"(f1.x));
            asm("cvt.rn.bf16x2.f32 %0, %1, %2;" : "=r"(p3) : "f"(f1.w), "f"(f1.z));
            STS128(Ab + r * RSTRIDE + c * 16, p0, p1, p2, p3);
        }
    }

    const int rA = w * 16 + (l >> 2);      // this lane's two output rows
    const int rB = rA + 8;
    const float zsqA = g_zsq[m0 + rA];
    const float zsqB = g_zsq[m0 + rB];
    const float emax = __int_as_float(g_emax_bits);
    const float W2A = 4.0f * 0.00390625f * sqrtf(zsqA) * emax + 1.0e-3f;
    const float W2B = 4.0f * 0.00390625f * sqrtf(zsqB) * emax + 1.0e-3f;
    float rowMinA = 3.4e38f, rowMinB = 3.4e38f;

    for (int kt = 0; kt < KC / KN; kt++) {
        __syncthreads();      // previous tile's smem reads complete
        // ---- load B tile (128 codes) + esq tile ----
        {
            const float* src = cb + (size_t)kt * KN * DDIM;
            #pragma unroll
            for (int it = 0; it < 16; it++) {
                int u = tid + it * 256;
                int r = u >> 5, c = u & 31;
                const float* p = src + (size_t)r * DDIM + c * 8;
                float4 f0 = __ldg(reinterpret_cast<const float4*>(p));
                float4 f1 = __ldg(reinterpret_cast<const float4*>(p + 4));
                uint32_t p0, p1, p2, p3;
                asm("cvt.rn.bf16x2.f32 %0, %1, %2;" : "=r"(p0) : "f"(f0.y), "f"(f0.x));
                asm("cvt.rn.bf16x2.f32 %0, %1, %2;" : "=r"(p1) : "f"(f0.w), "f"(f0.z));
                asm("cvt.rn.bf16x2.f32 %0, %1, %2;" : "=r"(p2) : "f"(f1.y), "f"(f1.x));
                asm("cvt.rn.bf16x2.f32 %0, %1, %2;" : "=r"(p3) : "f"(f1.w), "f"(f1.z));
                STS128(Bb + r * RSTRIDE + c * 16, p0, p1, p2, p3);
            }
            if (tid < KN) s_esq[tid] = g_esq[kt * KN + tid];
        }
        __syncthreads();

        // ---- MMA: 16 k-steps x 16 n-tiles per warp ----
        float acc[16][4];
        #pragma unroll
        for (int nt = 0; nt < 16; nt++)
            #pragma unroll
            for (int c = 0; c < 4; c++) acc[nt][c] = 0.f;

        const int mid = l >> 3, rr = l & 7;
        #pragma unroll
        for (int ks = 0; ks < 16; ks++) {
            uint32_t a0, a1, a2, a3;
            {
                uint32_t addr = Ab + (uint32_t)((w * 16 + (mid & 1) * 8 + rr) * RSTRIDE
                               + (ks * 2 + (mid >> 1)) * 16);
                LDMX4(a0, a1, a2, a3, addr);
            }
            #pragma unroll
            for (int ntp = 0; ntp < 8; ntp++) {
                uint32_t b0, b1, b2, b3;
                uint32_t addr = Bb + (uint32_t)((ntp * 16 + (mid >> 1) * 8 + rr) * RSTRIDE
                               + (ks * 2 + (mid & 1)) * 16);
                LDMX4(b0, b1, b2, b3, addr);
                MMA16816(acc[2 * ntp],     a0, a1, a2, a3, b0, b1);
                MMA16816(acc[2 * ntp + 1], a0, a1, a2, a3, b2, b3);
            }
        }

        // ---- pass 1: per-row running min (approximate distances) ----
        float tminA = 3.4e38f, tminB = 3.4e38f;
        #pragma unroll
        for (int nt = 0; nt < 16; nt++) {
            #pragma unroll
            for (int c = 0; c < 2; c++) {
                float esq = s_esq[nt * 8 + 2 * (l & 3) + c];
                float va = __fadd_rn(fmaf(-2.f, acc[nt][c],     zsqA), esq);
                float vb = __fadd_rn(fmaf(-2.f, acc[nt][2 + c], zsqB), esq);
                tminA = fminf(tminA, va);
                tminB = fminf(tminB, vb);
            }
        }
        tminA = fminf(tminA, __shfl_xor_sync(0xffffffffu, tminA, 1));
        tminA = fminf(tminA, __shfl_xor_sync(0xffffffffu, tminA, 2));
        tminB = fminf(tminB, __shfl_xor_sync(0xffffffffu, tminB, 1));
        tminB = fminf(tminB, __shfl_xor_sync(0xffffffffu, tminB, 2));
        rowMinA = fminf(rowMinA, tminA);
        rowMinB = fminf(rowMinB, tminB);
        const float thrA = rowMinA + W2A;
        const float thrB = rowMinB + W2B;

        // ---- pass 2: collect candidates within the guaranteed window ----
        #pragma unroll
        for (int nt = 0; nt < 16; nt++) {
            #pragma unroll
            for (int c = 0; c < 2; c++) {
                int colL = nt * 8 + 2 * (l & 3) + c;
                float esq = s_esq[colL];
                int col = kt * KN + colL;
                float va = __fadd_rn(fmaf(-2.f, acc[nt][c],     zsqA), esq);
                float vb = __fadd_rn(fmaf(-2.f, acc[nt][2 + c], zsqB), esq);
                if (va <= thrA) {
                    int s = atomicAdd(&s_cnt[rA], 1);
                    if (s < SLOTS) { s_candk[rA][s] = col; s_candv[rA][s] = va; }
                }
                if (vb <= thrB) {
                    int s = atomicAdd(&s_cnt[rB], 1);
                    if (s < SLOTS) { s_candk[rB][s] = col; s_candv[rB][s] = vb; }
                }
            }
        }
    }

    if ((l & 3) == 0) { s_rowmin[rA] = rowMinA; s_rowmin[rB] = rowMinB; }
    __syncthreads();

    // ---- selection: exact sequential-FMA recheck (bitwise ref pipeline) ----
    if (tid < BM) {
        const int row = tid;
        const float zsq = g_zsq[m0 + row];
        const float thr = s_rowmin[row]
                        + (4.0f * 0.00390625f * sqrtf(zsq) * emax + 1.0e-3f);
        const int cnt = s_cnt[row];
        const float* zr = z + (size_t)(m0 + row) * DDIM;
        float bv = 3.4e38f;
        int best = 0;
        if (cnt <= SLOTS) {
            for (int s = 0; s < cnt; s++) {
                if (s_candv[row][s] > thr) continue;
                int k = s_candk[row][s];
                const float* cr = cb + (size_t)k * DDIM;
                float acc = 0.f;
                for (int d = 0; d < DDIM; d++)
                    acc = fmaf(__ldg(zr + d), __ldg(cr + d), acc);
                float v = __fadd_rn(fmaf(-2.f, acc, zsq), g_esq[k]);
                if (v < bv || (v == bv && k < best)) { bv = v; best = k; }
            }
        } else {   // overflow fallback: full exact scan (vanishing probability)
            for (int k = 0; k < KC; k++) {
                const float* cr = cb + (size_t)k * DDIM;
                float acc = 0.f;
                for (int d = 0; d < DDIM; d++)
                    acc = fmaf(__ldg(zr + d), __ldg(cr + d), acc);
                float v = __fadd_rn(fmaf(-2.f, acc, zsq), g_esq[k]);
                if (v < bv) { bv = v; best = k; }   // ascending k: lowest on tie
            }
        }
        bidx[row] = best;
    }
    __syncthreads();

    // ---- gather + write: out[0:ND] = fl(z + fl(zq - z)) (STE), out[ND:] = zq
    const float4* cb4 = reinterpret_cast<const float4*>(cb);
    const float4* z4  = reinterpret_cast<const float4*>(z);
    float4* out4 = reinterpret_cast<float4*>(out);
    const long long base = (long long)m0 * (DDIM / 4);
    for (int e = tid; e < BM * (DDIM / 4); e += 256) {
        int r = e >> 6;
        int c = e & 63;
        int k = bidx[r];
        float4 q  = cb4[k * (DDIM / 4) + c];
        float4 ze = z4[base + (long long)r * (DDIM / 4) + c];
        float4 st;
        st.x = __fadd_rn(ze.x, __fsub_rn(q.x, ze.x));
        st.y = __fadd_rn(ze.y, __fsub_rn(q.y, ze.y));
        st.z = __fadd_rn(ze.z, __fsub_rn(q.z, ze.z));
        st.w = __fadd_rn(ze.w, __fsub_rn(q.w, ze.w));
        out4[base + (long long)r * (DDIM / 4) + c] = st;
        if (qoff4 > 0)
            out4[qoff4 + base + (long long)r * (DDIM / 4) + c] = q;
    }
}

extern "C" void kernel_launch(void* const* d_in, const int* in_sizes, int n_in,
                              void* d_out, int out_size) {
    const float* z  = (const float*)d_in[0];
    const float* cb = (const float*)d_in[1];
    int Nrows = in_sizes[0] / DDIM;
    long long ND = (long long)Nrows * DDIM;
    long long qoff4 = ((long long)out_size >= 2 * ND) ? (ND / 4) : 0;

    static int smem_set = 0;
    if (!smem_set) {
        cudaFuncSetAttribute(vq_main, cudaFuncAttributeMaxDynamicSharedMemorySize,
                             DYN_SMEM);
        smem_set = 1;
    }

    int nbz = Nrows / 128;
    rowsq_all<<<nbz + KC / 128, 128>>>(z, cb, nbz);
    vq_main<<<Nrows / BM, 256, DYN_SMEM>>>(z, cb, (float*)d_out, qoff4);
}